// round 6
// baseline (speedup 1.0000x reference)
#include <cuda_runtime.h>

#define NBLK 148
#define TPB  256
#define GSZ  20971520   // 128*512*320
#define NC   163840     // 512*320

// ---------------- static device scratch ----------------
__device__ __align__(16) float d_T0[29 * 1280];     // layer0 gate preact per label (incl bias), perm cols
__device__ __align__(16) float d_B1[1280];          // layer1 bias, perm cols
__device__ __align__(16) float d_W0[320 * 1280];    // w_hh0^T perm: [k][p]
__device__ __align__(16) float d_W1[640 * 1280];    // [w_ih1; w_hh1]^T perm: [k][p]
__device__ __align__(16) float d_A0[2][320 * 512];  // layer0 h, [parity][c][n]
__device__ __align__(16) float d_A1[2][640 * 512];  // layer1 input: rows<320 ys0, rows>=320 h1
__device__ __align__(16) float d_C0[512 * 320];     // layer0 c, [n][c]  (epilogue-coalesced)
__device__ __align__(16) float d_C1[512 * 320];     // layer1 c, [n][c]
__device__ unsigned g_gen, g_cnt;

// ---------------- helpers ----------------
__device__ __forceinline__ unsigned long long splat2(float v) {
    unsigned long long r; asm("mov.b64 %0, {%1, %1};" : "=l"(r) : "f"(v)); return r;
}
__device__ __forceinline__ void fma2(unsigned long long& d, unsigned long long a, unsigned long long b) {
    asm("fma.rn.f32x2 %0, %1, %2, %0;" : "+l"(d) : "l"(a), "l"(b));
}
__device__ __forceinline__ float2 un2(unsigned long long v) {
    float lo, hi; asm("mov.b64 {%0, %1}, %2;" : "=f"(lo), "=f"(hi) : "l"(v));
    return make_float2(lo, hi);
}
__device__ __forceinline__ float sigf(float v)   { return __fdividef(1.0f, 1.0f + __expf(-v)); }
__device__ __forceinline__ float tanhf_(float v) { return __fdividef(2.0f, 1.0f + __expf(-2.0f * v)) - 1.0f; }
__device__ __forceinline__ void cp16(void* dst, const void* src) {
    unsigned d = (unsigned)__cvta_generic_to_shared(dst);
    asm volatile("cp.async.cg.shared.global [%0], [%1], 16;" :: "r"(d), "l"(src));
}
__device__ __forceinline__ unsigned ld_acq(const unsigned* p) {
    unsigned v; asm volatile("ld.acquire.gpu.u32 %0, [%1];" : "=r"(v) : "l"(p) : "memory"); return v;
}
__device__ __forceinline__ void st_rel(unsigned* p, unsigned v) {
    asm volatile("st.release.gpu.u32 [%0], %1;" :: "l"(p), "r"(v) : "memory");
}

// ---------------- prep kernels ----------------
// perm col p: cell = p>>2, gate = p&3; natural j = gate*320 + cell.
__global__ void prep_wt(const float* __restrict__ w_ih, const float* __restrict__ w_hh) {
    const int st = gridDim.x * blockDim.x;
    const int i0 = blockIdx.x * blockDim.x + threadIdx.x;
    for (int i = i0; i < 320 * 1280; i += st) {
        const int k = i / 1280, p = i - k * 1280;
        const int j = (p & 3) * 320 + (p >> 2);
        d_W0[i] = w_hh[j * 320 + k];
    }
    for (int i = i0; i < 640 * 1280; i += st) {
        const int k = i / 1280, p = i - k * 1280;
        const int j = (p & 3) * 320 + (p >> 2);
        d_W1[i] = (k < 320) ? w_ih[409600 + j * 320 + k]
                            : w_hh[409600 + j * 320 + (k - 320)];
    }
}

// T0[v][p] = bias0 + dot(embed[v], w_ih0[j]); v==28 (SOS) -> bias only.
__global__ void prep_t0(const float* __restrict__ emb, const float* __restrict__ w_ih,
                        const float* __restrict__ b_ih, const float* __restrict__ b_hh) {
    const int v = blockIdx.x / 10;
    const int p = (blockIdx.x % 10) * 128 + threadIdx.x;
    const int j = (p & 3) * 320 + (p >> 2);
    float acc = b_ih[j] + b_hh[j];
    if (v < 28) {
        const float* er = emb + v * 320;
        const float* wr = w_ih + j * 320;
#pragma unroll 4
        for (int k = 0; k < 320; k += 4) {
            const float4 e = *reinterpret_cast<const float4*>(er + k);
            const float4 w = *reinterpret_cast<const float4*>(wr + k);
            acc += e.x * w.x + e.y * w.y + e.z * w.z + e.w * w.w;
        }
    }
    d_T0[v * 1280 + p] = acc;
}

__global__ void prep_state(const float* __restrict__ h0, const float* __restrict__ c0,
                           const float* __restrict__ b_ih, const float* __restrict__ b_hh) {
    const int st = gridDim.x * blockDim.x;
    const int i0 = blockIdx.x * blockDim.x + threadIdx.x;
    for (int i = i0; i < NC; i += st) {
        const int n = i / 320, c = i - n * 320;
        d_A0[0][c * 512 + n]         = h0[i];         // layer0 h read at s=0 (parity 0)
        d_A1[1][(320 + c) * 512 + n] = h0[NC + i];    // layer1 h read at s=1 (parity 1)
        d_C0[i] = c0[i];                              // [n][c] natural copy
        d_C1[i] = c0[NC + i];
    }
    for (int i = i0; i < 1280; i += st) {
        const int j = (i & 3) * 320 + (i >> 2);
        d_B1[i] = b_ih[1280 + j] + b_hh[1280 + j];
    }
    if (i0 == 0) { g_gen = 0u; g_cnt = 0u; }
}

// ---------------- persistent LSTM kernel ----------------
// interval s (0..128): layer0 step s (s<128) + layer1 step s-1 (s>=1).
// Static schedule: 80 heavy tiles (layer1, K=640) -> CTAs 0..79;
// 80 light tiles (layer0, K=320) -> CTAs 80..147 (first 12 get 2).
// tile: 64 rows x 128 perm cols. Warp grid 2x4 (warp = 32 rows x 32 cols);
// thread = 8 rows x 1 cell (4 perm cols). k-chunk = 32, double buffered.
__global__ void __launch_bounds__(TPB, 1)
lstm_pers(const int* __restrict__ x, float* __restrict__ out) {
    __shared__ __align__(16) float sA[2][32 * 64];    // 16KB
    __shared__ __align__(16) float sB[2][32 * 128];   // 32KB
    float* hstage = &sB[0][0];                        // 32*65 floats, aliases sB post-GEMM
    const int tx = threadIdx.x;
    const int lane = tx & 31, wid = tx >> 5;
    const int wr = wid >> 2, wc = wid & 3;            // warp 2x4 grid
    const int lr = lane >> 3, lc = lane & 7;          // lane 4x8 grid
    const int rowOff = (wr << 5) + (lr << 3);         // 0..56, thread's first row in tile
    const int colOff = (wc << 5) + (lc << 2);         // 0..124, thread's cell (4 perm cols)
    const int b = blockIdx.x;

    for (int s = 0; s < 129; ++s) {
        const int par = s & 1;
        int tiles[2]; int nt = 0;
        if (b < 80) {
            if (s >= 1) tiles[nt++] = b;                       // heavy (layer1)
        } else if (s < 128) {
            const int j = b - 80;
            tiles[nt++] = 80 + j;                              // light (layer0)
            if (j < 12) tiles[nt++] = 80 + 68 + j;
        }

        for (int ti = 0; ti < nt; ++ti) {
            const int tk   = tiles[ti];
            const int lay1 = (tk < 80);
            const int q    = lay1 ? tk : tk - 80;
            const int n0   = (q / 10) * 64;
            const int p0   = (q % 10) * 128;
            const float* Wt = lay1 ? d_W1 : d_W0;
            const float* At = lay1 ? d_A1[par] : d_A0[par];
            const int nch  = lay1 ? 20 : 10;                   // K/32

            unsigned long long acc[8][2];
#pragma unroll
            for (int r = 0; r < 8; ++r) { acc[r][0] = 0ull; acc[r][1] = 0ull; }

            auto prefetch = [&](int ch, int buf) {
                const int k0 = ch << 5;
#pragma unroll
                for (int it = 0; it < 2; ++it) {   // A: 32x64 floats
                    const int idx = tx + it * 256;
                    const int kk = idx >> 4, nn = (idx & 15) * 4;
                    cp16(&sA[buf][kk * 64 + nn], At + (k0 + kk) * 512 + n0 + nn);
                }
#pragma unroll
                for (int it = 0; it < 4; ++it) {   // B: 32x128 floats
                    const int idx = tx + it * 256;
                    const int kk = idx >> 5, pp = (idx & 31) * 4;
                    cp16(&sB[buf][kk * 128 + pp], Wt + (k0 + kk) * 1280 + p0 + pp);
                }
                asm volatile("cp.async.commit_group;");
            };

            prefetch(0, 0);
            prefetch(1, 1);

            for (int ch = 0; ch < nch; ++ch) {
                const int buf = ch & 1;
                if (ch + 1 < nch) asm volatile("cp.async.wait_group 1;");
                else              asm volatile("cp.async.wait_group 0;");
                __syncthreads();
#pragma unroll 8
                for (int kk = 0; kk < 32; ++kk) {
                    const float4 a0 = *reinterpret_cast<const float4*>(&sA[buf][kk * 64 + rowOff]);
                    const float4 a1 = *reinterpret_cast<const float4*>(&sA[buf][kk * 64 + rowOff + 4]);
                    const ulonglong2 bb = *reinterpret_cast<const ulonglong2*>(&sB[buf][kk * 128 + colOff]);
                    unsigned long long a;
                    a = splat2(a0.x); fma2(acc[0][0], a, bb.x); fma2(acc[0][1], a, bb.y);
                    a = splat2(a0.y); fma2(acc[1][0], a, bb.x); fma2(acc[1][1], a, bb.y);
                    a = splat2(a0.z); fma2(acc[2][0], a, bb.x); fma2(acc[2][1], a, bb.y);
                    a = splat2(a0.w); fma2(acc[3][0], a, bb.x); fma2(acc[3][1], a, bb.y);
                    a = splat2(a1.x); fma2(acc[4][0], a, bb.x); fma2(acc[4][1], a, bb.y);
                    a = splat2(a1.y); fma2(acc[5][0], a, bb.x); fma2(acc[5][1], a, bb.y);
                    a = splat2(a1.z); fma2(acc[6][0], a, bb.x); fma2(acc[6][1], a, bb.y);
                    a = splat2(a1.w); fma2(acc[7][0], a, bb.x); fma2(acc[7][1], a, bb.y);
                }
                __syncthreads();
                if (ch + 2 < nch) prefetch(ch + 2, buf);
            }

            // ---- epilogue: LSTM cell update; thread owns 8 rows x 1 cell ----
            const int cell = (p0 >> 2) + (wc << 3) + lc;
            float* Cst = lay1 ? d_C1 : d_C0;
            const int u = lay1 ? (s - 1) : s;
            float4 bia;
            if (lay1) bia = *reinterpret_cast<const float4*>(&d_B1[cell * 4]);
            float hv[8];
#pragma unroll
            for (int r = 0; r < 8; ++r) {
                const int n = n0 + rowOff + r;
                const float2 g01 = un2(acc[r][0]);
                const float2 g23 = un2(acc[r][1]);
                float gi, gf, gg, go;
                if (lay1) {
                    gi = g01.x + bia.x; gf = g01.y + bia.y;
                    gg = g23.x + bia.z; go = g23.y + bia.w;
                } else {
                    const int lab = x[u * 512 + n];   // 0..28; 28=SOS -> bias-only row
                    const float4 t0 = *reinterpret_cast<const float4*>(&d_T0[lab * 1280 + (cell << 2)]);
                    gi = g01.x + t0.x; gf = g01.y + t0.y;
                    gg = g23.x + t0.z; go = g23.y + t0.w;
                }
                gi = sigf(gi); gf = sigf(gf); gg = tanhf_(gg); go = sigf(go);
                const int ci = n * 320 + cell;        // [n][c] coalesced across lc
                const float c = gf * Cst[ci] + gi * gg;
                Cst[ci] = c;
                const float h = go * tanhf_(c);
                hv[r] = h;
                if (lay1) {
                    out[u * NC + ci] = h;             // g output, coalesced
                    if (u == 127) { out[GSZ + NC + ci] = h; out[GSZ + 3 * NC + ci] = c; }
                } else {
                    if (u == 127) { out[GSZ + ci] = h; out[GSZ + 2 * NC + ci] = c; }
                }
            }

            // ---- h write transposed [c][n] via padded smem stage (coalesced) ----
            __syncthreads();                           // GEMM smem reads done; sB reusable
            {
                const int cidx = (wc << 3) + lc;       // 0..31 cell index in tile
#pragma unroll
                for (int r = 0; r < 8; ++r)
                    hstage[cidx * 65 + rowOff + r] = hv[r];
            }
            __syncthreads();
            {
                const int cell0 = p0 >> 2;
                float* dstA = lay1 ? &d_A1[par ^ 1][(320 + cell0) * 512 + n0]
                                   : &d_A0[par ^ 1][cell0 * 512 + n0];
                float* dstB = lay1 ? nullptr : &d_A1[par ^ 1][cell0 * 512 + n0];
#pragma unroll
                for (int i = tx; i < 2048; i += 256) {
                    const int cl = i >> 6, rw = i & 63;
                    const float v = hstage[cl * 65 + rw];
                    dstA[cl * 512 + rw] = v;
                    if (!lay1) dstB[cl * 512 + rw] = v;  // ys0 feed for layer1
                }
            }
            __syncthreads();                           // protect hstage before next prefetch
        }

        // ---- grid barrier (release/acquire) ----
        __syncthreads();
        if (tx == 0) {
            __threadfence();
            const unsigned arrived = atomicAdd(&g_cnt, 1u);
            if (arrived == NBLK - 1) {
                g_cnt = 0u;
                __threadfence();
                st_rel(&g_gen, (unsigned)(s + 1));
            } else {
                while (ld_acq(&g_gen) <= (unsigned)s) __nanosleep(40);
            }
        }
        __syncthreads();
    }
}

// ---------------- launcher ----------------
extern "C" void kernel_launch(void* const* d_in, const int* in_sizes, int n_in,
                              void* d_out, int out_size) {
    const int*   x    = (const int*)d_in[0];
    const float* h0   = (const float*)d_in[1];
    const float* c0   = (const float*)d_in[2];
    const float* emb  = (const float*)d_in[3];
    const float* w_ih = (const float*)d_in[4];
    const float* w_hh = (const float*)d_in[5];
    const float* b_ih = (const float*)d_in[6];
    const float* b_hh = (const float*)d_in[7];

    prep_wt<<<512, 256>>>(w_ih, w_hh);
    prep_t0<<<290, 128>>>(emb, w_ih, b_ih, b_hh);
    prep_state<<<256, 256>>>(h0, c0, b_ih, b_hh);
    lstm_pers<<<NBLK, TPB>>>(x, (float*)d_out);
}

// round 8
// speedup vs baseline: 1.6697x; 1.6697x over previous
#include <cuda_runtime.h>
#include <cstdint>

#define NBLK 148
#define TPB  256
#define GSZ  20971520   // 128*512*320
#define NC   163840     // 512*320

// ---------------- static device scratch ----------------
__device__ __align__(16) float d_T0[29 * 1280];    // layer0 gate preact per label (incl bias), cell-major
__device__ __align__(16) float d_B1[1280];         // layer1 bias, cell-major
__device__ __align__(16) float d_W0m[1280 * 320];  // layer0 w_hh, [p][k], mma-perm rows, tf32-rounded
__device__ __align__(16) float d_W1m[1280 * 640];  // layer1 [w_ih|w_hh], [p][k], mma-perm, tf32-rounded
__device__ __align__(16) float d_A0[2][512 * 320]; // layer0 h, [parity][n][c], tf32-rounded
__device__ __align__(16) float d_A1[2][512 * 640]; // layer1 input [n][ys0(320)|h1(320)], tf32-rounded
__device__ __align__(16) float d_C0[512 * 320];    // layer0 c, [n][c], exact
__device__ __align__(16) float d_C1[512 * 320];    // layer1 c
__device__ unsigned g_gen, g_cnt;

// ---------------- helpers ----------------
__device__ __forceinline__ float sigf(float v)   { return __fdividef(1.0f, 1.0f + __expf(-v)); }
__device__ __forceinline__ float tanhf_(float v) { return __fdividef(2.0f, 1.0f + __expf(-2.0f * v)) - 1.0f; }
__device__ __forceinline__ void cp16(void* dst, const void* src) {
    unsigned d = (unsigned)__cvta_generic_to_shared(dst);
    asm volatile("cp.async.cg.shared.global [%0], [%1], 16;" :: "r"(d), "l"(src));
}
__device__ __forceinline__ unsigned ld_acq(const unsigned* p) {
    unsigned v; asm volatile("ld.acquire.gpu.u32 %0, [%1];" : "=r"(v) : "l"(p) : "memory"); return v;
}
__device__ __forceinline__ void st_rel(unsigned* p, unsigned v) {
    asm volatile("st.release.gpu.u32 [%0], %1;" :: "l"(p), "r"(v) : "memory");
}
__device__ __forceinline__ float tf32_rne(float f) {
    uint32_t u = __float_as_uint(f);
    u = (u + 0xFFFu + ((u >> 13) & 1u)) & 0xFFFFE000u;
    return __uint_as_float(u);
}
__device__ __forceinline__ uint32_t smem_u32(const void* p) {
    return (uint32_t)__cvta_generic_to_shared(p);
}
__device__ __forceinline__ void ldm4(uint32_t& r0, uint32_t& r1, uint32_t& r2, uint32_t& r3, uint32_t addr) {
    asm volatile("ldmatrix.sync.aligned.m8n8.x4.shared.b16 {%0,%1,%2,%3}, [%4];"
                 : "=r"(r0), "=r"(r1), "=r"(r2), "=r"(r3) : "r"(addr));
}
__device__ __forceinline__ void mma8(float* d, const uint32_t* a, uint32_t b0, uint32_t b1) {
    asm volatile(
        "mma.sync.aligned.m16n8k8.row.col.f32.tf32.tf32.f32 "
        "{%0,%1,%2,%3}, {%4,%5,%6,%7}, {%8,%9}, {%0,%1,%2,%3};"
        : "+f"(d[0]), "+f"(d[1]), "+f"(d[2]), "+f"(d[3])
        : "r"(a[0]), "r"(a[1]), "r"(a[2]), "r"(a[3]), "r"(b0), "r"(b1));
}

// mma-perm: output col p -> natural gate row j.
// In-tile col t = p&127: wc=t>>5, r=t&31, ni=r>>3, rm=r&7, qc=rm>>1, low=rm&1.
// cell-in-128 = wc*8 + qc + (ni>>1)*4; gate = (ni&1)*2 + low.
__host__ __device__ __forceinline__ int perm_j(int p) {
    const int t = p & 127;
    const int wc = t >> 5, r = t & 31;
    const int ni = r >> 3, rm = r & 7;
    const int cell = (p >> 7) * 32 + wc * 8 + (rm >> 1) + ((ni >> 1) << 2);
    const int gate = ((ni & 1) << 1) | (rm & 1);
    return gate * 320 + cell;
}

// ---------------- prep kernels ----------------
__global__ void prep_wt(const float* __restrict__ w_ih, const float* __restrict__ w_hh) {
    const int st = gridDim.x * blockDim.x;
    const int i0 = blockIdx.x * blockDim.x + threadIdx.x;
    for (int i = i0; i < 1280 * 320; i += st) {
        const int p = i / 320, k = i - p * 320;
        d_W0m[i] = tf32_rne(w_hh[perm_j(p) * 320 + k]);
    }
    for (int i = i0; i < 1280 * 640; i += st) {
        const int p = i / 640, k = i - p * 640;
        const int j = perm_j(p);
        d_W1m[i] = tf32_rne((k < 320) ? w_ih[409600 + j * 320 + k]
                                      : w_hh[409600 + j * 320 + (k - 320)]);
    }
}

// T0[v][cell*4+gate] = bias0 + dot(embed[v], w_ih0); v==28 (SOS) -> bias only. Exact fp32.
__global__ void prep_t0(const float* __restrict__ emb, const float* __restrict__ w_ih,
                        const float* __restrict__ b_ih, const float* __restrict__ b_hh) {
    const int v = blockIdx.x / 10;
    const int p = (blockIdx.x % 10) * 128 + threadIdx.x;
    const int j = (p & 3) * 320 + (p >> 2);          // cell-major: p = cell*4+gate
    float acc = b_ih[j] + b_hh[j];
    if (v < 28) {
        const float* er = emb + v * 320;
        const float* wr = w_ih + j * 320;
#pragma unroll 4
        for (int k = 0; k < 320; k += 4) {
            const float4 e = *reinterpret_cast<const float4*>(er + k);
            const float4 w = *reinterpret_cast<const float4*>(wr + k);
            acc += e.x * w.x + e.y * w.y + e.z * w.z + e.w * w.w;
        }
    }
    d_T0[v * 1280 + p] = acc;
}

__global__ void prep_state(const float* __restrict__ h0, const float* __restrict__ c0,
                           const float* __restrict__ b_ih, const float* __restrict__ b_hh) {
    const int st = gridDim.x * blockDim.x;
    const int i0 = blockIdx.x * blockDim.x + threadIdx.x;
    for (int i = i0; i < NC; i += st) {
        const int n = i / 320, c = i - n * 320;
        d_A0[0][i] = tf32_rne(h0[i]);                      // layer0 h at s=0 (parity 0)
        d_A1[1][n * 640 + 320 + c] = tf32_rne(h0[NC + i]); // layer1 h at s=1 (parity 1)
        d_C0[i] = c0[i];
        d_C1[i] = c0[NC + i];
    }
    for (int i = i0; i < 1280; i += st) {
        const int j = (i & 3) * 320 + (i >> 2);            // cell-major
        d_B1[i] = b_ih[1280 + j] + b_hh[1280 + j];
    }
    if (i0 == 0) { g_gen = 0u; g_cnt = 0u; }
}

// ---------------- persistent LSTM kernel (mma.sync tf32) ----------------
// interval s (0..128): layer0 step s (s<128) + layer1 step s-1 (s>=1).
// Static schedule: 80 heavy (layer1, K=640) -> CTAs 0..79;
// 80 light (layer0, K=320) -> CTAs 80..147 (first 12 get 2).
// Tile 64 rows x 128 perm cols; 8 warps 2x4; warp tile 32x32 (2 m-atoms x 4 n-atoms).
// K-chunk 16 (2 k8 steps), 3-stage cp.async ring. Smem row stride 20 floats (80B).
__global__ void __launch_bounds__(TPB, 1)
lstm_pers(const int* __restrict__ x, float* __restrict__ out) {
    __shared__ __align__(16) float smem[3 * 3840];   // stage: A 64x20 | B 128x20 (45KB)
    const int tx = threadIdx.x;
    const int lane = tx & 31, wid = tx >> 5;
    const int wr = wid >> 2, wc = wid & 3;
    const int g_ = lane >> 2, q_ = lane & 3;
    const int sub = lane >> 3, subrow = lane & 7;
    const int b = blockIdx.x;
    const uint32_t sbase = smem_u32(smem);

    // per-lane ldmatrix byte offsets (within a stage)
    uint32_t aoff[2], boff[2];
#pragma unroll
    for (int mi = 0; mi < 2; ++mi) {
        const int rowA = wr * 32 + mi * 16 + (sub & 1) * 8 + subrow;
        aoff[mi] = rowA * 80 + (sub >> 1) * 16;
    }
#pragma unroll
    for (int nb = 0; nb < 2; ++nb) {
        const int rowB = wc * 32 + nb * 16 + (sub >> 1) * 8 + subrow;
        boff[nb] = 5120 + rowB * 80 + (sub & 1) * 16;    // B starts at float 1280
    }

    for (int s = 0; s < 129; ++s) {
        const int par = s & 1;
        int tiles[2]; int nt = 0;
        if (b < 80) {
            if (s >= 1) tiles[nt++] = b;                  // heavy (layer1)
        } else if (s < 128) {
            const int j = b - 80;
            tiles[nt++] = 80 + j;                         // light (layer0)
            if (j < 12) tiles[nt++] = 80 + 68 + j;
        }

        for (int ti = 0; ti < nt; ++ti) {
            const int tk = tiles[ti];
            const int heavy = (tk < 80);
            const int q = heavy ? tk : tk - 80;
            const int n0 = (q / 10) * 64, p0 = (q % 10) * 128;
            const int Kdim = heavy ? 640 : 320;
            const int nch = Kdim >> 4;
            const float* W = heavy ? d_W1m : d_W0m;
            const float* Amat = heavy ? d_A1[par] : d_A0[par];

            float acc[2][4][4];
#pragma unroll
            for (int mi = 0; mi < 2; ++mi)
#pragma unroll
                for (int ni = 0; ni < 4; ++ni)
#pragma unroll
                    for (int e = 0; e < 4; ++e) acc[mi][ni][e] = 0.0f;

            auto prefetch = [&](int ch) {
                if (ch < nch) {
                    float* stg = smem + (ch % 3) * 3840;
                    const int k0 = ch << 4;
                    {   // A: 64 rows x 16 floats = 256 cp16
                        const int row = tx >> 2, seg = tx & 3;
                        cp16(stg + row * 20 + seg * 4, Amat + (n0 + row) * Kdim + k0 + seg * 4);
                    }
#pragma unroll
                    for (int it = 0; it < 2; ++it) {   // B: 128 rows x 16 = 512 cp16
                        const int idx = tx + it * 256;
                        const int row = idx >> 2, seg = idx & 3;
                        cp16(stg + 1280 + row * 20 + seg * 4, W + (p0 + row) * Kdim + k0 + seg * 4);
                    }
                }
                asm volatile("cp.async.commit_group;" ::: "memory");
            };

            prefetch(0); prefetch(1); prefetch(2);

            for (int ch = 0; ch < nch; ++ch) {
                asm volatile("cp.async.wait_group 2;" ::: "memory");
                __syncthreads();
                const uint32_t st = sbase + (uint32_t)(ch % 3) * 15360u;
#pragma unroll
                for (int ks = 0; ks < 2; ++ks) {
                    uint32_t a[2][4], bb[2][4];
                    ldm4(a[0][0], a[0][1], a[0][2], a[0][3], st + aoff[0] + ks * 32);
                    ldm4(a[1][0], a[1][1], a[1][2], a[1][3], st + aoff[1] + ks * 32);
                    ldm4(bb[0][0], bb[0][1], bb[0][2], bb[0][3], st + boff[0] + ks * 32);
                    ldm4(bb[1][0], bb[1][1], bb[1][2], bb[1][3], st + boff[1] + ks * 32);
#pragma unroll
                    for (int mi = 0; mi < 2; ++mi) {
                        mma8(acc[mi][0], a[mi], bb[0][0], bb[0][1]);
                        mma8(acc[mi][1], a[mi], bb[0][2], bb[0][3]);
                        mma8(acc[mi][2], a[mi], bb[1][0], bb[1][1]);
                        mma8(acc[mi][3], a[mi], bb[1][2], bb[1][3]);
                    }
                }
                __syncthreads();
                prefetch(ch + 3);
            }

            // ---- epilogue: thread owns rows {wr*32+mi*16+g_, +8} x cells {q_, q_+4} ----
            const int u = heavy ? (s - 1) : s;
            float* Cst = heavy ? d_C1 : d_C0;
#pragma unroll
            for (int mi = 0; mi < 2; ++mi) {
#pragma unroll
                for (int rs = 0; rs < 2; ++rs) {
                    const int n = n0 + wr * 32 + mi * 16 + g_ + rs * 8;
                    const float* tb = heavy ? d_B1 : (d_T0 + x[u * 512 + n] * 1280);
#pragma unroll
                    for (int cs = 0; cs < 2; ++cs) {
                        const int cellg = (p0 >> 2) + wc * 8 + q_ + cs * 4;
                        const float4 t = *reinterpret_cast<const float4*>(tb + cellg * 4);
                        const float pi = acc[mi][cs * 2 + 0][rs * 2 + 0] + t.x;
                        const float pf = acc[mi][cs * 2 + 0][rs * 2 + 1] + t.y;
                        const float pg = acc[mi][cs * 2 + 1][rs * 2 + 0] + t.z;
                        const float po = acc[mi][cs * 2 + 1][rs * 2 + 1] + t.w;
                        const float ii = sigf(pi), ff = sigf(pf);
                        const float gg = tanhf_(pg), oo = sigf(po);
                        const int ci = n * 320 + cellg;
                        const float c = ff * Cst[ci] + ii * gg;
                        Cst[ci] = c;
                        const float h = oo * tanhf_(c);
                        const float hr = tf32_rne(h);
                        if (heavy) {
                            out[(size_t)u * NC + ci] = h;
                            d_A1[par ^ 1][n * 640 + 320 + cellg] = hr;
                            if (u == 127) { out[GSZ + NC + ci] = h; out[GSZ + 3 * NC + ci] = c; }
                        } else {
                            d_A0[par ^ 1][ci] = hr;
                            d_A1[par ^ 1][n * 640 + cellg] = hr;
                            if (u == 127) { out[GSZ + ci] = h; out[GSZ + 2 * NC + ci] = c; }
                        }
                    }
                }
            }
        }

        // ---- grid barrier (release/acquire) ----
        __syncthreads();
        if (tx == 0) {
            __threadfence();
            const unsigned arrived = atomicAdd(&g_cnt, 1u);
            if (arrived == NBLK - 1) {
                g_cnt = 0u;
                __threadfence();
                st_rel(&g_gen, (unsigned)(s + 1));
            } else {
                while (ld_acq(&g_gen) <= (unsigned)s) __nanosleep(40);
            }
        }
        __syncthreads();
    }
}

// ---------------- launcher ----------------
extern "C" void kernel_launch(void* const* d_in, const int* in_sizes, int n_in,
                              void* d_out, int out_size) {
    const int*   x    = (const int*)d_in[0];
    const float* h0   = (const float*)d_in[1];
    const float* c0   = (const float*)d_in[2];
    const float* emb  = (const float*)d_in[3];
    const float* w_ih = (const float*)d_in[4];
    const float* w_hh = (const float*)d_in[5];
    const float* b_ih = (const float*)d_in[6];
    const float* b_hh = (const float*)d_in[7];

    prep_wt<<<512, 256>>>(w_ih, w_hh);
    prep_t0<<<290, 128>>>(emb, w_ih, b_ih, b_hh);
    prep_state<<<256, 256>>>(h0, c0, b_ih, b_hh);
    lstm_pers<<<NBLK, TPB>>>(x, (float*)d_out);
}

// round 9
// speedup vs baseline: 1.6922x; 1.0135x over previous
#include <cuda_runtime.h>
#include <cstdint>

#define NBLK 148
#define TPB  256
#define GSZ  20971520   // 128*512*320
#define NC   163840     // 512*320

// smem: 4 stages; stage = A 64x36 + B 128x36 floats = 6912 floats = 27648 B
#define STG_FLOATS 6912
#define STG_BYTES  27648
#define B_BASE_B   9216          // 64*144
#define SMEM_TOTAL (4 * STG_BYTES)

// ---------------- static device scratch ----------------
__device__ __align__(16) float d_T0[29 * 1280];    // layer0 gate preact per label (incl bias), cell-major
__device__ __align__(16) float d_B1[1280];         // layer1 bias, cell-major
__device__ __align__(16) float d_W0m[1280 * 320];  // layer0 w_hh, [p][k], mma-perm rows, tf32-rounded
__device__ __align__(16) float d_W1m[1280 * 640];  // layer1 [w_ih|w_hh], [p][k], mma-perm, tf32-rounded
__device__ __align__(16) float d_A0[2][512 * 320]; // layer0 h, [parity][n][c], tf32-rounded
__device__ __align__(16) float d_A1[2][512 * 640]; // layer1 input [n][ys0(320)|h1(320)], tf32-rounded
__device__ __align__(16) float d_C0[512 * 320];    // layer0 c, [n][c], exact
__device__ __align__(16) float d_C1[512 * 320];    // layer1 c
__device__ unsigned g_gen, g_cnt;

// ---------------- helpers ----------------
__device__ __forceinline__ float sigf(float v)   { return __fdividef(1.0f, 1.0f + __expf(-v)); }
__device__ __forceinline__ float tanhf_(float v) { return __fdividef(2.0f, 1.0f + __expf(-2.0f * v)) - 1.0f; }
__device__ __forceinline__ void cp16(void* dst, const void* src) {
    unsigned d = (unsigned)__cvta_generic_to_shared(dst);
    asm volatile("cp.async.cg.shared.global [%0], [%1], 16;" :: "r"(d), "l"(src));
}
__device__ __forceinline__ unsigned ld_acq(const unsigned* p) {
    unsigned v; asm volatile("ld.acquire.gpu.u32 %0, [%1];" : "=r"(v) : "l"(p) : "memory"); return v;
}
__device__ __forceinline__ void st_rel(unsigned* p, unsigned v) {
    asm volatile("st.release.gpu.u32 [%0], %1;" :: "l"(p), "r"(v) : "memory");
}
__device__ __forceinline__ float tf32_rne(float f) {
    uint32_t u = __float_as_uint(f);
    u = (u + 0xFFFu + ((u >> 13) & 1u)) & 0xFFFFE000u;
    return __uint_as_float(u);
}
__device__ __forceinline__ uint32_t smem_u32(const void* p) {
    return (uint32_t)__cvta_generic_to_shared(p);
}
__device__ __forceinline__ void ldm4(uint32_t& r0, uint32_t& r1, uint32_t& r2, uint32_t& r3, uint32_t addr) {
    asm volatile("ldmatrix.sync.aligned.m8n8.x4.shared.b16 {%0,%1,%2,%3}, [%4];"
                 : "=r"(r0), "=r"(r1), "=r"(r2), "=r"(r3) : "r"(addr));
}
__device__ __forceinline__ void mma8(float* d, const uint32_t* a, uint32_t b0, uint32_t b1) {
    asm volatile(
        "mma.sync.aligned.m16n8k8.row.col.f32.tf32.tf32.f32 "
        "{%0,%1,%2,%3}, {%4,%5,%6,%7}, {%8,%9}, {%0,%1,%2,%3};"
        : "+f"(d[0]), "+f"(d[1]), "+f"(d[2]), "+f"(d[3])
        : "r"(a[0]), "r"(a[1]), "r"(a[2]), "r"(a[3]), "r"(b0), "r"(b1));
}

// mma-perm: output col p -> natural gate row j.
__host__ __device__ __forceinline__ int perm_j(int p) {
    const int t = p & 127;
    const int wc = t >> 5, r = t & 31;
    const int ni = r >> 3, rm = r & 7;
    const int cell = (p >> 7) * 32 + wc * 8 + (rm >> 1) + ((ni >> 1) << 2);
    const int gate = ((ni & 1) << 1) | (rm & 1);
    return gate * 320 + cell;
}

// ---------------- prep kernels ----------------
__global__ void prep_wt(const float* __restrict__ w_ih, const float* __restrict__ w_hh) {
    const int st = gridDim.x * blockDim.x;
    const int i0 = blockIdx.x * blockDim.x + threadIdx.x;
    for (int i = i0; i < 1280 * 320; i += st) {
        const int p = i / 320, k = i - p * 320;
        d_W0m[i] = tf32_rne(w_hh[perm_j(p) * 320 + k]);
    }
    for (int i = i0; i < 1280 * 640; i += st) {
        const int p = i / 640, k = i - p * 640;
        const int j = perm_j(p);
        d_W1m[i] = tf32_rne((k < 320) ? w_ih[409600 + j * 320 + k]
                                      : w_hh[409600 + j * 320 + (k - 320)]);
    }
}

// T0[v][cell*4+gate] = bias0 + dot(embed[v], w_ih0); v==28 (SOS) -> bias only. Exact fp32.
__global__ void prep_t0(const float* __restrict__ emb, const float* __restrict__ w_ih,
                        const float* __restrict__ b_ih, const float* __restrict__ b_hh) {
    const int v = blockIdx.x / 10;
    const int p = (blockIdx.x % 10) * 128 + threadIdx.x;
    const int j = (p & 3) * 320 + (p >> 2);          // cell-major: p = cell*4+gate
    float acc = b_ih[j] + b_hh[j];
    if (v < 28) {
        const float* er = emb + v * 320;
        const float* wr = w_ih + j * 320;
#pragma unroll 4
        for (int k = 0; k < 320; k += 4) {
            const float4 e = *reinterpret_cast<const float4*>(er + k);
            const float4 w = *reinterpret_cast<const float4*>(wr + k);
            acc += e.x * w.x + e.y * w.y + e.z * w.z + e.w * w.w;
        }
    }
    d_T0[v * 1280 + p] = acc;
}

__global__ void prep_state(const float* __restrict__ h0, const float* __restrict__ c0,
                           const float* __restrict__ b_ih, const float* __restrict__ b_hh) {
    const int st = gridDim.x * blockDim.x;
    const int i0 = blockIdx.x * blockDim.x + threadIdx.x;
    for (int i = i0; i < NC; i += st) {
        const int n = i / 320, c = i - n * 320;
        d_A0[0][i] = tf32_rne(h0[i]);                      // layer0 h at s=0 (parity 0)
        d_A1[1][n * 640 + 320 + c] = tf32_rne(h0[NC + i]); // layer1 h at s=1 (parity 1)
        d_C0[i] = c0[i];
        d_C1[i] = c0[NC + i];
    }
    for (int i = i0; i < 1280; i += st) {
        const int j = (i & 3) * 320 + (i >> 2);            // cell-major
        d_B1[i] = b_ih[1280 + j] + b_hh[1280 + j];
    }
    if (i0 == 0) { g_gen = 0u; g_cnt = 0u; }
}

// ---------------- persistent LSTM kernel (mma.sync tf32) ----------------
// interval s (0..128): layer0 step s (s<128) + layer1 step s-1 (s>=1).
// Static schedule: 80 heavy (layer1, K=640) -> CTAs 0..79;
// 80 light (layer0, K=320) -> CTAs 80..147 (first 12 get 2).
// Tile 64 rows x 128 perm cols; 8 warps 2x4; warp tile 32x32.
// K-chunk 32 (4 k8 steps), 4-stage ring, prefetch depth 2, ONE sync per iter.
// Smem row stride 36 floats (144 B) -> conflict-free ldmatrix (4r mod 32 distinct).
__global__ void __launch_bounds__(TPB, 1)
lstm_pers(const int* __restrict__ x, float* __restrict__ out) {
    extern __shared__ __align__(16) float smem[];
    const int tx = threadIdx.x;
    const int lane = tx & 31, wid = tx >> 5;
    const int wr = wid >> 2, wc = wid & 3;
    const int g_ = lane >> 2, q_ = lane & 3;
    const int sub = lane >> 3, subrow = lane & 7;
    const int b = blockIdx.x;
    const uint32_t sbase = smem_u32(smem);

    // per-lane ldmatrix byte offsets (within a stage); k-step adds ks*32
    uint32_t aoff[2], boff[2];
#pragma unroll
    for (int mi = 0; mi < 2; ++mi) {
        const int rowA = wr * 32 + mi * 16 + (sub & 1) * 8 + subrow;
        aoff[mi] = rowA * 144 + (sub >> 1) * 16;
    }
#pragma unroll
    for (int nb = 0; nb < 2; ++nb) {
        const int rowB = wc * 32 + nb * 16 + (sub >> 1) * 8 + subrow;
        boff[nb] = B_BASE_B + rowB * 144 + (sub & 1) * 16;
    }

    for (int s = 0; s < 129; ++s) {
        const int par = s & 1;
        int tiles[2]; int nt = 0;
        if (b < 80) {
            if (s >= 1) tiles[nt++] = b;                  // heavy (layer1)
        } else if (s < 128) {
            const int j = b - 80;
            tiles[nt++] = 80 + j;                         // light (layer0)
            if (j < 12) tiles[nt++] = 80 + 68 + j;
        }

        for (int ti = 0; ti < nt; ++ti) {
            const int tk = tiles[ti];
            const int heavy = (tk < 80);
            const int q = heavy ? tk : tk - 80;
            const int n0 = (q / 10) * 64, p0 = (q % 10) * 128;
            const int Kdim = heavy ? 640 : 320;
            const int nch = Kdim >> 5;
            const float* W = heavy ? d_W1m : d_W0m;
            const float* Amat = heavy ? d_A1[par] : d_A0[par];

            float acc[2][4][4];
#pragma unroll
            for (int mi = 0; mi < 2; ++mi)
#pragma unroll
                for (int ni = 0; ni < 4; ++ni)
#pragma unroll
                    for (int e = 0; e < 4; ++e) acc[mi][ni][e] = 0.0f;

            auto prefetch = [&](int ch) {
                if (ch < nch) {
                    float* stg = smem + (ch & 3) * STG_FLOATS;
                    const int k0 = ch << 5;
#pragma unroll
                    for (int it = 0; it < 2; ++it) {   // A: 64 rows x 32 floats = 512 cp16
                        const int idx = tx + it * 256;
                        const int row = idx >> 3, seg = idx & 7;
                        cp16(stg + row * 36 + seg * 4, Amat + (n0 + row) * Kdim + k0 + seg * 4);
                    }
#pragma unroll
                    for (int it = 0; it < 4; ++it) {   // B: 128 rows x 32 = 1024 cp16
                        const int idx = tx + it * 256;
                        const int row = idx >> 3, seg = idx & 7;
                        cp16(stg + 2304 + row * 36 + seg * 4, W + (p0 + row) * Kdim + k0 + seg * 4);
                    }
                }
                asm volatile("cp.async.commit_group;" ::: "memory");
            };

            prefetch(0); prefetch(1);

            for (int ch = 0; ch < nch; ++ch) {
                prefetch(ch + 2);                          // writes stage (ch+2)&3: safe (gap 2 syncs)
                asm volatile("cp.async.wait_group 2;" ::: "memory");
                __syncthreads();
                const uint32_t st = sbase + (uint32_t)(ch & 3) * STG_BYTES;
#pragma unroll
                for (int ks = 0; ks < 4; ++ks) {
                    uint32_t a[2][4], bb[2][4];
                    ldm4(a[0][0], a[0][1], a[0][2], a[0][3], st + aoff[0] + ks * 32);
                    ldm4(a[1][0], a[1][1], a[1][2], a[1][3], st + aoff[1] + ks * 32);
                    ldm4(bb[0][0], bb[0][1], bb[0][2], bb[0][3], st + boff[0] + ks * 32);
                    ldm4(bb[1][0], bb[1][1], bb[1][2], bb[1][3], st + boff[1] + ks * 32);
#pragma unroll
                    for (int mi = 0; mi < 2; ++mi) {
                        mma8(acc[mi][0], a[mi], bb[0][0], bb[0][1]);
                        mma8(acc[mi][1], a[mi], bb[0][2], bb[0][3]);
                        mma8(acc[mi][2], a[mi], bb[1][0], bb[1][1]);
                        mma8(acc[mi][3], a[mi], bb[1][2], bb[1][3]);
                    }
                }
            }

            // ---- epilogue: thread owns rows {wr*32+mi*16+g_, +8} x cells {q_, q_+4} ----
            const int u = heavy ? (s - 1) : s;
            float* Cst = heavy ? d_C1 : d_C0;
#pragma unroll
            for (int mi = 0; mi < 2; ++mi) {
#pragma unroll
                for (int rs = 0; rs < 2; ++rs) {
                    const int n = n0 + wr * 32 + mi * 16 + g_ + rs * 8;
                    const float* tb = heavy ? d_B1 : (d_T0 + x[u * 512 + n] * 1280);
#pragma unroll
                    for (int cs = 0; cs < 2; ++cs) {
                        const int cellg = (p0 >> 2) + wc * 8 + q_ + cs * 4;
                        const float4 t = *reinterpret_cast<const float4*>(tb + cellg * 4);
                        const float pi = acc[mi][cs * 2 + 0][rs * 2 + 0] + t.x;
                        const float pf = acc[mi][cs * 2 + 0][rs * 2 + 1] + t.y;
                        const float pg = acc[mi][cs * 2 + 1][rs * 2 + 0] + t.z;
                        const float po = acc[mi][cs * 2 + 1][rs * 2 + 1] + t.w;
                        const float ii = sigf(pi), ff = sigf(pf);
                        const float gg = tanhf_(pg), oo = sigf(po);
                        const int ci = n * 320 + cellg;
                        const float c = ff * Cst[ci] + ii * gg;
                        Cst[ci] = c;
                        const float h = oo * tanhf_(c);
                        const float hr = tf32_rne(h);
                        if (heavy) {
                            out[(size_t)u * NC + ci] = h;
                            d_A1[par ^ 1][n * 640 + 320 + cellg] = hr;
                            if (u == 127) { out[GSZ + NC + ci] = h; out[GSZ + 3 * NC + ci] = c; }
                        } else {
                            d_A0[par ^ 1][ci] = hr;
                            d_A1[par ^ 1][n * 640 + cellg] = hr;
                            if (u == 127) { out[GSZ + ci] = h; out[GSZ + 2 * NC + ci] = c; }
                        }
                    }
                }
            }
            __syncthreads();   // protect stages: laggard reads vs next tile's prefetch
        }

        // ---- grid barrier (release/acquire) ----
        __syncthreads();
        if (tx == 0) {
            __threadfence();
            const unsigned arrived = atomicAdd(&g_cnt, 1u);
            if (arrived == NBLK - 1) {
                g_cnt = 0u;
                __threadfence();
                st_rel(&g_gen, (unsigned)(s + 1));
            } else {
                while (ld_acq(&g_gen) <= (unsigned)s) __nanosleep(32);
            }
        }
        __syncthreads();
    }
}

// ---------------- launcher ----------------
extern "C" void kernel_launch(void* const* d_in, const int* in_sizes, int n_in,
                              void* d_out, int out_size) {
    const int*   x    = (const int*)d_in[0];
    const float* h0   = (const float*)d_in[1];
    const float* c0   = (const float*)d_in[2];
    const float* emb  = (const float*)d_in[3];
    const float* w_ih = (const float*)d_in[4];
    const float* w_hh = (const float*)d_in[5];
    const float* b_ih = (const float*)d_in[6];
    const float* b_hh = (const float*)d_in[7];

    cudaFuncSetAttribute(lstm_pers, cudaFuncAttributeMaxDynamicSharedMemorySize, SMEM_TOTAL);

    prep_wt<<<512, 256>>>(w_ih, w_hh);
    prep_t0<<<290, 128>>>(emb, w_ih, b_ih, b_hh);
    prep_state<<<256, 256>>>(h0, c0, b_ih, b_hh);
    lstm_pers<<<NBLK, TPB, SMEM_TOTAL>>>(x, (float*)d_out);
}

// round 11
// speedup vs baseline: 2.1296x; 1.2585x over previous
#include <cuda_runtime.h>
#include <cstdint>

#define NBLK 148
#define TPB  256
#define GSZ  20971520   // 128*512*320
#define NC   163840     // 512*320

// dynamic smem: 3 A-stages (16KB) | mbars | resident B
#define STG_B     16384
#define MBAR_OFF  49152
#define BRES_OFF  49216
#define BSLOT_B   82944          // light B slot stride: 64*324*4
#define SMEM_DYN  215104         // 49216 + 165888

// ---------------- static device scratch ----------------
__device__ __align__(16) float d_T0[29 * 1280];      // layer0 preact per label (incl bias), cell-major
__device__ __align__(16) float d_B1[1280];           // layer1 bias, cell-major
__device__ __align__(16) float d_W0m[1280 * 320];    // layer0 w_hh, [p][k], perm64 rows, tf32
__device__ __align__(16) float d_W1m[1280 * 640];    // layer1 [w_ih|w_hh], [p][k], perm64, tf32
__device__ __align__(16) float d_A0c[2][10 * 512 * 32]; // layer0 h, chunk-major swizzled
__device__ __align__(16) float d_A1c[2][20 * 512 * 32]; // layer1 in: ch 0..9 ys0, 10..19 h1
__device__ __align__(16) float d_C0[512 * 320];      // layer0 c, [n][c]
__device__ __align__(16) float d_C1[512 * 320];      // layer1 c
__device__ unsigned g_genA[4 * 32];
__device__ unsigned g_cntA[4 * 32];

// ---------------- helpers ----------------
__device__ __forceinline__ float sigf(float v)   { return __fdividef(1.0f, 1.0f + __expf(-v)); }
__device__ __forceinline__ float tanhf_(float v) { return __fdividef(2.0f, 1.0f + __expf(-2.0f * v)) - 1.0f; }
__device__ __forceinline__ unsigned ld_acq(const unsigned* p) {
    unsigned v; asm volatile("ld.acquire.gpu.u32 %0, [%1];" : "=r"(v) : "l"(p) : "memory"); return v;
}
__device__ __forceinline__ void st_rel(unsigned* p, unsigned v) {
    asm volatile("st.release.gpu.u32 [%0], %1;" :: "l"(p), "r"(v) : "memory");
}
__device__ __forceinline__ float tf32_rne(float f) {
    uint32_t u = __float_as_uint(f);
    u = (u + 0xFFFu + ((u >> 13) & 1u)) & 0xFFFFE000u;
    return __uint_as_float(u);
}
__device__ __forceinline__ void ldm4(uint32_t& r0, uint32_t& r1, uint32_t& r2, uint32_t& r3, uint32_t addr) {
    asm volatile("ldmatrix.sync.aligned.m8n8.x4.shared.b16 {%0,%1,%2,%3}, [%4];"
                 : "=r"(r0), "=r"(r1), "=r"(r2), "=r"(r3) : "r"(addr));
}
__device__ __forceinline__ void mma8(float* d, const uint32_t* a, uint32_t b0, uint32_t b1) {
    asm volatile(
        "mma.sync.aligned.m16n8k8.row.col.f32.tf32.tf32.f32 "
        "{%0,%1,%2,%3}, {%4,%5,%6,%7}, {%8,%9}, {%0,%1,%2,%3};"
        : "+f"(d[0]), "+f"(d[1]), "+f"(d[2]), "+f"(d[3])
        : "r"(a[0]), "r"(a[1]), "r"(a[2]), "r"(a[3]), "r"(b0), "r"(b1));
}
__device__ __forceinline__ void bulk_ld(uint32_t dst, const void* src, uint32_t mbar) {
    asm volatile("mbarrier.arrive.expect_tx.shared.b64 _, [%0], %1;" :: "r"(mbar), "r"(16384u) : "memory");
    asm volatile("cp.async.bulk.shared::cluster.global.mbarrier::complete_tx::bytes [%0], [%1], %2, [%3];"
                 :: "r"(dst), "l"(src), "r"(16384u), "r"(mbar) : "memory");
}
__device__ __forceinline__ void waitp(uint32_t mb, int ph) {
    asm volatile(
        "{\n\t.reg .pred P;\n"
        "W%=:\n\t"
        "mbarrier.try_wait.parity.acquire.cta.shared::cta.b64 P, [%0], %1, 0x989680;\n\t"
        "@P bra.uni D%=;\n\t"
        "bra.uni W%=;\n"
        "D%=:\n\t}"
        :: "r"(mb), "r"((unsigned)ph) : "memory");
}

// perm64: output col p (tile width 64) -> natural gate row j = gate*320 + cell.
__host__ __device__ __forceinline__ int perm_j64(int p) {
    const int t = p & 63;
    const int wc = t >> 5, r = t & 31;
    const int ni = r >> 3, rm = r & 7;
    const int cell = (p >> 6) * 16 + wc * 8 + (rm >> 1) + ((ni >> 1) << 2);
    const int gate = ((ni & 1) << 1) | (rm & 1);
    return gate * 320 + cell;
}
// chunk-major swizzled A index (within a chunk) for (n, cell&31)
__host__ __device__ __forceinline__ int aswz(int n, int c32) {
    return n * 32 + (c32 ^ ((n & 7) << 2));
}

// ---------------- prep kernels ----------------
__global__ void prep_wt(const float* __restrict__ w_ih, const float* __restrict__ w_hh) {
    const int st = gridDim.x * blockDim.x;
    const int i0 = blockIdx.x * blockDim.x + threadIdx.x;
    for (int i = i0; i < 1280 * 320; i += st) {
        const int p = i / 320, k = i - p * 320;
        d_W0m[i] = tf32_rne(w_hh[perm_j64(p) * 320 + k]);
    }
    for (int i = i0; i < 1280 * 640; i += st) {
        const int p = i / 640, k = i - p * 640;
        const int j = perm_j64(p);
        d_W1m[i] = tf32_rne((k < 320) ? w_ih[409600 + j * 320 + k]
                                      : w_hh[409600 + j * 320 + (k - 320)]);
    }
}

__global__ void prep_t0(const float* __restrict__ emb, const float* __restrict__ w_ih,
                        const float* __restrict__ b_ih, const float* __restrict__ b_hh) {
    const int v = blockIdx.x / 10;
    const int p = (blockIdx.x % 10) * 128 + threadIdx.x;
    const int j = (p & 3) * 320 + (p >> 2);          // cell-major: p = cell*4+gate
    float acc = b_ih[j] + b_hh[j];
    if (v < 28) {
        const float* er = emb + v * 320;
        const float* wr = w_ih + j * 320;
#pragma unroll 4
        for (int k = 0; k < 320; k += 4) {
            const float4 e = *reinterpret_cast<const float4*>(er + k);
            const float4 w = *reinterpret_cast<const float4*>(wr + k);
            acc += e.x * w.x + e.y * w.y + e.z * w.z + e.w * w.w;
        }
    }
    d_T0[v * 1280 + p] = acc;
}

__global__ void prep_state(const float* __restrict__ h0, const float* __restrict__ c0,
                           const float* __restrict__ b_ih, const float* __restrict__ b_hh) {
    const int st = gridDim.x * blockDim.x;
    const int i0 = blockIdx.x * blockDim.x + threadIdx.x;
    for (int i = i0; i < NC; i += st) {
        const int n = i / 320, c = i - n * 320;
        d_A0c[0][(c >> 5) * 16384 + aswz(n, c & 31)] = tf32_rne(h0[i]);
        d_A1c[1][(10 + (c >> 5)) * 16384 + aswz(n, c & 31)] = tf32_rne(h0[NC + i]);
        d_C0[i] = c0[i];
        d_C1[i] = c0[NC + i];
    }
    for (int i = i0; i < 1280; i += st) {
        const int j = (i & 3) * 320 + (i >> 2);
        d_B1[i] = b_ih[1280 + j] + b_hh[1280 + j];
    }
    if (i0 < 4) { g_genA[i0 * 32] = 0u; g_cntA[i0 * 32] = 0u; }
}

// ---------------- persistent LSTM kernel ----------------
// 4 row groups x 128 rows; per group 37 CTAs: r<20 heavy (K=640, p0=r*64),
// r>=20 light (K=320): CTA r2=r-20 owns light tile r2 and (r2<3) also 17+r2.
// Tile 128 rows x 64 perm cols; warps 4x2; warp 32x32; thread 8x(2 cells).
// B resident in smem (stride Kdim+4 floats); A staged via cp.async.bulk, 3-stage ring.
// A chunk stride in global = 512*32 floats; group slice (128 rows) is contiguous 16KB.
__global__ void __launch_bounds__(TPB, 1)
lstm_pers(const int* __restrict__ x, float* __restrict__ out) {
    extern __shared__ __align__(16) char dsm[];
    const uint32_t sbase = (uint32_t)__cvta_generic_to_shared(dsm);
    const uint32_t mb0 = sbase + MBAR_OFF;
    float* Bres = (float*)(dsm + BRES_OFF);
    const uint32_t Bres32 = sbase + BRES_OFF;

    const int tx = threadIdx.x;
    const int lane = tx & 31, wid = tx >> 5;
    const int wr = wid >> 1, wc = wid & 1;
    const int g_ = lane >> 2, q_ = lane & 3;
    const int sub = lane >> 3, subrow = lane & 7;
    const int b = blockIdx.x;
    const int grp = b / 37, r = b - grp * 37;
    const int heavy = (r < 20);
    const int n0 = grp * 128;
    const int Kdim = heavy ? 640 : 320;
    const int nch = Kdim >> 5;
    const int sbf = Kdim + 4;                      // B smem stride (floats)
    const int ntile = heavy ? 1 : ((r - 20) < 3 ? 2 : 1);
    int p0s[2];
    if (heavy) { p0s[0] = r * 64; p0s[1] = 0; }
    else       { p0s[0] = (r - 20) * 64; p0s[1] = (17 + (r - 20)) * 64; }

    // ---- one-time: init mbars, load resident B ----
    if (tx == 0) {
#pragma unroll
        for (int i = 0; i < 3; ++i)
            asm volatile("mbarrier.init.shared.b64 [%0], %1;" :: "r"(mb0 + i * 8), "r"(1u) : "memory");
    }
    for (int ti = 0; ti < ntile; ++ti) {
        const float* Wg = heavy ? (d_W1m + p0s[ti] * 640) : (d_W0m + p0s[ti] * 320);
        float* Bs = Bres + ti * (BSLOT_B / 4);
        const int nseg = Kdim >> 2;                // float4 per col
        for (int i = tx; i < 64 * nseg; i += TPB) {
            const int col = i / nseg, seg = i - col * nseg;
            *reinterpret_cast<float4*>(Bs + col * sbf + seg * 4) =
                *reinterpret_cast<const float4*>(Wg + col * Kdim + seg * 4);
        }
    }
    __syncthreads();

    // ldsm offsets
    uint32_t aoffb[2];
    const uint32_t xr = (uint32_t)(subrow << 4);
#pragma unroll
    for (int mi = 0; mi < 2; ++mi) {
        const int rowA = wr * 32 + mi * 16 + (sub & 1) * 8 + subrow;
        aoffb[mi] = (uint32_t)(rowA * 128 + (sub >> 1) * 16);
    }
    uint32_t bbase[2];
#pragma unroll
    for (int nb = 0; nb < 2; ++nb) {
        const int rowB = wc * 32 + nb * 16 + (sub >> 1) * 8 + subrow;
        bbase[nb] = Bres32 + (uint32_t)(rowB * sbf * 4 + (sub & 1) * 16);
    }

    int ph[3] = {0, 0, 0};

    for (int s = 0; s < 129; ++s) {
        const int par = s & 1;
        const int active = heavy ? (s >= 1) : (s < 128);
        if (active) {
            const float* Asrc = heavy ? d_A1c[par] : d_A0c[par];
            const int u = heavy ? (s - 1) : s;
            float* Cst = heavy ? d_C1 : d_C0;

            for (int ti = 0; ti < ntile; ++ti) {
                const int p0 = p0s[ti];
                const uint32_t bslot = (uint32_t)(ti * BSLOT_B);

                // prefetch c-state + labels (hide epilogue latency)
                float cpre[2][2][2];
                int labv[2][2];
#pragma unroll
                for (int mi = 0; mi < 2; ++mi)
#pragma unroll
                    for (int rs = 0; rs < 2; ++rs) {
                        const int n = n0 + wr * 32 + mi * 16 + g_ + rs * 8;
                        if (!heavy) labv[mi][rs] = x[u * 512 + n];
#pragma unroll
                        for (int cs = 0; cs < 2; ++cs) {
                            const int cellg = (p0 >> 2) + wc * 8 + q_ + cs * 4;
                            cpre[mi][rs][cs] = Cst[n * 320 + cellg];
                        }
                    }

                float acc[2][4][4];
#pragma unroll
                for (int mi = 0; mi < 2; ++mi)
#pragma unroll
                    for (int ni = 0; ni < 4; ++ni)
#pragma unroll
                        for (int e = 0; e < 4; ++e) acc[mi][ni][e] = 0.0f;

                if (tx == 0) {
#pragma unroll
                    for (int c = 0; c < 3; ++c)
                        if (c < nch)
                            bulk_ld(sbase + (c % 3) * STG_B,
                                    Asrc + (size_t)c * 16384 + n0 * 32, mb0 + (c % 3) * 8);
                }

                for (int ch = 0; ch < nch; ++ch) {
                    const int sl = ch % 3;
                    waitp(mb0 + sl * 8, ph[sl]); ph[sl] ^= 1;
                    const uint32_t stA = sbase + (uint32_t)sl * STG_B;
                    const uint32_t chB = bslot + (uint32_t)ch * 128;
#pragma unroll
                    for (int ks = 0; ks < 4; ++ks) {
                        uint32_t a[2][4], bb[2][4];
                        ldm4(a[0][0], a[0][1], a[0][2], a[0][3],
                             stA + ((aoffb[0] + ks * 32) ^ xr));
                        ldm4(a[1][0], a[1][1], a[1][2], a[1][3],
                             stA + ((aoffb[1] + ks * 32) ^ xr));
                        ldm4(bb[0][0], bb[0][1], bb[0][2], bb[0][3], bbase[0] + chB + ks * 32);
                        ldm4(bb[1][0], bb[1][1], bb[1][2], bb[1][3], bbase[1] + chB + ks * 32);
#pragma unroll
                        for (int mi = 0; mi < 2; ++mi) {
                            mma8(acc[mi][0], a[mi], bb[0][0], bb[0][1]);
                            mma8(acc[mi][1], a[mi], bb[0][2], bb[0][3]);
                            mma8(acc[mi][2], a[mi], bb[1][0], bb[1][1]);
                            mma8(acc[mi][3], a[mi], bb[1][2], bb[1][3]);
                        }
                    }
                    __syncthreads();                 // readers done with stage sl
                    if (tx == 0 && ch + 3 < nch)
                        bulk_ld(sbase + sl * STG_B,
                                Asrc + (size_t)(ch + 3) * 16384 + n0 * 32, mb0 + sl * 8);
                }

                // ---- epilogue ----
#pragma unroll
                for (int mi = 0; mi < 2; ++mi) {
#pragma unroll
                    for (int rs = 0; rs < 2; ++rs) {
                        const int n = n0 + wr * 32 + mi * 16 + g_ + rs * 8;
                        const float* tb = heavy ? d_B1 : (d_T0 + labv[mi][rs] * 1280);
#pragma unroll
                        for (int cs = 0; cs < 2; ++cs) {
                            const int cellg = (p0 >> 2) + wc * 8 + q_ + cs * 4;
                            const float4 t = *reinterpret_cast<const float4*>(tb + cellg * 4);
                            const float pi = acc[mi][cs * 2 + 0][rs * 2 + 0] + t.x;
                            const float pf = acc[mi][cs * 2 + 0][rs * 2 + 1] + t.y;
                            const float pg = acc[mi][cs * 2 + 1][rs * 2 + 0] + t.z;
                            const float po = acc[mi][cs * 2 + 1][rs * 2 + 1] + t.w;
                            const float ii = sigf(pi), ff = sigf(pf);
                            const float gg = tanhf_(pg), oo = sigf(po);
                            const int ci = n * 320 + cellg;
                            const float c = ff * cpre[mi][rs][cs] + ii * gg;
                            Cst[ci] = c;
                            const float h = oo * tanhf_(c);
                            const float hr = tf32_rne(h);
                            const int wsw = aswz(n, cellg & 31);
                            if (heavy) {
                                out[(size_t)u * NC + ci] = h;
                                d_A1c[par ^ 1][(10 + (cellg >> 5)) * 16384 + wsw] = hr;
                                if (u == 127) { out[GSZ + NC + ci] = h; out[GSZ + 3 * NC + ci] = c; }
                            } else {
                                d_A0c[par ^ 1][(cellg >> 5) * 16384 + wsw] = hr;
                                d_A1c[par ^ 1][(cellg >> 5) * 16384 + wsw] = hr;
                                if (u == 127) { out[GSZ + ci] = h; out[GSZ + 2 * NC + ci] = c; }
                            }
                        }
                    }
                }
            }
        }

        // ---- group barrier (37 CTAs, release/acquire) ----
        __syncthreads();
        if (tx == 0) {
            __threadfence();
            const unsigned arrived = atomicAdd(&g_cntA[grp * 32], 1u);
            if (arrived == 36u) {
                g_cntA[grp * 32] = 0u;
                __threadfence();
                st_rel(&g_genA[grp * 32], (unsigned)(s + 1));
            } else {
                while (ld_acq(&g_genA[grp * 32]) <= (unsigned)s) __nanosleep(32);
            }
        }
        __syncthreads();
    }
}

// ---------------- launcher ----------------
extern "C" void kernel_launch(void* const* d_in, const int* in_sizes, int n_in,
                              void* d_out, int out_size) {
    const int*   x    = (const int*)d_in[0];
    const float* h0   = (const float*)d_in[1];
    const float* c0   = (const float*)d_in[2];
    const float* emb  = (const float*)d_in[3];
    const float* w_ih = (const float*)d_in[4];
    const float* w_hh = (const float*)d_in[5];
    const float* b_ih = (const float*)d_in[6];
    const float* b_hh = (const float*)d_in[7];

    cudaFuncSetAttribute(lstm_pers, cudaFuncAttributeMaxDynamicSharedMemorySize, SMEM_DYN);

    prep_wt<<<512, 256>>>(w_ih, w_hh);
    prep_t0<<<290, 128>>>(emb, w_ih, b_ih, b_hh);
    prep_state<<<256, 256>>>(h0, c0, b_ih, b_hh);
    lstm_pers<<<NBLK, TPB, SMEM_DYN>>>(x, (float*)d_out);
}

// round 12
// speedup vs baseline: 2.5605x; 1.2023x over previous
#include <cuda_runtime.h>
#include <cstdint>

#define NBLK 148
#define TPB  512
#define GSZ  20971520   // 128*512*320
#define NC   163840     // 512*320

// dynamic smem: 2 A-stages (32KB each) | mbars | resident B (swizzled, unpadded)
#define STG_B     32768
#define MBAR_OFF  65536
#define BRES_OFF  65664
#define BSLOT_B   81920          // light B slot: 64 cols x 320 floats x 4
#define SMEM_DYN  229504         // 65664 + 163840

// ---------------- static device scratch ----------------
__device__ __align__(16) float d_T0[29 * 1280];      // layer0 preact per label (incl bias), cell-major
__device__ __align__(16) float d_B1[1280];           // layer1 bias, cell-major
__device__ __align__(16) float d_W0m[1280 * 320];    // layer0 w_hh, [p][k], perm16 rows, tf32
__device__ __align__(16) float d_W1m[1280 * 640];    // layer1 [w_ih|w_hh], [p][k], perm16, tf32
__device__ __align__(16) float d_A0c[2][5 * 512 * 64];  // layer0 h, 64-chunk-major swizzled
__device__ __align__(16) float d_A1c[2][10 * 512 * 64]; // layer1 in: ch 0..4 ys0, 5..9 h1
__device__ __align__(16) float d_C0[512 * 320];      // layer0 c, [n][c]
__device__ __align__(16) float d_C1[512 * 320];      // layer1 c
__device__ unsigned g_genA[4 * 32];
__device__ unsigned g_cntA[4 * 32];

// ---------------- helpers ----------------
__device__ __forceinline__ float sigf(float v)   { return __fdividef(1.0f, 1.0f + __expf(-v)); }
__device__ __forceinline__ float tanhf_(float v) { return __fdividef(2.0f, 1.0f + __expf(-2.0f * v)) - 1.0f; }
__device__ __forceinline__ unsigned ld_acq(const unsigned* p) {
    unsigned v; asm volatile("ld.acquire.gpu.u32 %0, [%1];" : "=r"(v) : "l"(p) : "memory"); return v;
}
__device__ __forceinline__ void st_rel(unsigned* p, unsigned v) {
    asm volatile("st.release.gpu.u32 [%0], %1;" :: "l"(p), "r"(v) : "memory");
}
__device__ __forceinline__ float tf32_rne(float f) {
    uint32_t u = __float_as_uint(f);
    u = (u + 0xFFFu + ((u >> 13) & 1u)) & 0xFFFFE000u;
    return __uint_as_float(u);
}
__device__ __forceinline__ void ldm4(uint32_t& r0, uint32_t& r1, uint32_t& r2, uint32_t& r3, uint32_t addr) {
    asm volatile("ldmatrix.sync.aligned.m8n8.x4.shared.b16 {%0,%1,%2,%3}, [%4];"
                 : "=r"(r0), "=r"(r1), "=r"(r2), "=r"(r3) : "r"(addr));
}
__device__ __forceinline__ void mma8(float* d, const uint32_t* a, uint32_t b0, uint32_t b1) {
    asm volatile(
        "mma.sync.aligned.m16n8k8.row.col.f32.tf32.tf32.f32 "
        "{%0,%1,%2,%3}, {%4,%5,%6,%7}, {%8,%9}, {%0,%1,%2,%3};"
        : "+f"(d[0]), "+f"(d[1]), "+f"(d[2]), "+f"(d[3])
        : "r"(a[0]), "r"(a[1]), "r"(a[2]), "r"(a[3]), "r"(b0), "r"(b1));
}
__device__ __forceinline__ void bulk_ld(uint32_t dst, const void* src, uint32_t mbar) {
    asm volatile("mbarrier.arrive.expect_tx.shared.b64 _, [%0], %1;" :: "r"(mbar), "r"(32768u) : "memory");
    asm volatile("cp.async.bulk.shared::cluster.global.mbarrier::complete_tx::bytes [%0], [%1], %2, [%3];"
                 :: "r"(dst), "l"(src), "r"(32768u), "r"(mbar) : "memory");
}
__device__ __forceinline__ void waitp(uint32_t mb, int ph) {
    asm volatile(
        "{\n\t.reg .pred P;\n"
        "W%=:\n\t"
        "mbarrier.try_wait.parity.acquire.cta.shared::cta.b64 P, [%0], %1, 0x989680;\n\t"
        "@P bra.uni D%=;\n\t"
        "bra.uni W%=;\n"
        "D%=:\n\t}"
        :: "r"(mb), "r"((unsigned)ph) : "memory");
}

// perm16: output col p -> natural gate row j = gate*320 + cell.
// tile a = p>>6 (16 cells), tcol = p&63: wcol = tcol>>4, t = tcol&15, ni = t>>3, rm = t&7.
// cell = a*16 + wcol*4 + (rm>>1); gate = (ni<<1)|(rm&1).
__host__ __device__ __forceinline__ int perm_j16(int p) {
    const int tcol = p & 63;
    const int wcol = tcol >> 4, t = tcol & 15;
    const int ni = t >> 3, rm = t & 7;
    const int cell = (p >> 6) * 16 + wcol * 4 + (rm >> 1);
    const int gate = ((ni & 1) << 1) | (rm & 1);
    return gate * 320 + cell;
}
// 64-wide chunk-major swizzled A float index within a chunk for (n, c64)
__host__ __device__ __forceinline__ int aswz64(int n, int c64) {
    const int seg = c64 >> 2;
    return n * 64 + (((seg ^ (n & 7)) << 2) | (c64 & 3));
}

// ---------------- prep kernels ----------------
__global__ void prep_wt(const float* __restrict__ w_ih, const float* __restrict__ w_hh) {
    const int st = gridDim.x * blockDim.x;
    const int i0 = blockIdx.x * blockDim.x + threadIdx.x;
    for (int i = i0; i < 1280 * 320; i += st) {
        const int p = i / 320, k = i - p * 320;
        d_W0m[i] = tf32_rne(w_hh[perm_j16(p) * 320 + k]);
    }
    for (int i = i0; i < 1280 * 640; i += st) {
        const int p = i / 640, k = i - p * 640;
        const int j = perm_j16(p);
        d_W1m[i] = tf32_rne((k < 320) ? w_ih[409600 + j * 320 + k]
                                      : w_hh[409600 + j * 320 + (k - 320)]);
    }
}

__global__ void prep_t0(const float* __restrict__ emb, const float* __restrict__ w_ih,
                        const float* __restrict__ b_ih, const float* __restrict__ b_hh) {
    const int v = blockIdx.x / 10;
    const int p = (blockIdx.x % 10) * 128 + threadIdx.x;
    const int j = (p & 3) * 320 + (p >> 2);          // cell-major: p = cell*4+gate
    float acc = b_ih[j] + b_hh[j];
    if (v < 28) {
        const float* er = emb + v * 320;
        const float* wr = w_ih + j * 320;
#pragma unroll 4
        for (int k = 0; k < 320; k += 4) {
            const float4 e = *reinterpret_cast<const float4*>(er + k);
            const float4 w = *reinterpret_cast<const float4*>(wr + k);
            acc += e.x * w.x + e.y * w.y + e.z * w.z + e.w * w.w;
        }
    }
    d_T0[v * 1280 + p] = acc;
}

__global__ void prep_state(const float* __restrict__ h0, const float* __restrict__ c0,
                           const float* __restrict__ b_ih, const float* __restrict__ b_hh) {
    const int st = gridDim.x * blockDim.x;
    const int i0 = blockIdx.x * blockDim.x + threadIdx.x;
    for (int i = i0; i < NC; i += st) {
        const int n = i / 320, c = i - n * 320;
        d_A0c[0][(c >> 6) * 32768 + aswz64(n, c & 63)] = tf32_rne(h0[i]);
        d_A1c[1][(5 + (c >> 6)) * 32768 + aswz64(n, c & 63)] = tf32_rne(h0[NC + i]);
        d_C0[i] = c0[i];
        d_C1[i] = c0[NC + i];
    }
    for (int i = i0; i < 1280; i += st) {
        const int j = (i & 3) * 320 + (i >> 2);
        d_B1[i] = b_ih[1280 + j] + b_hh[1280 + j];
    }
    if (i0 < 4) { g_genA[i0 * 32] = 0u; g_cntA[i0 * 32] = 0u; }
}

// ---------------- persistent LSTM kernel ----------------
// 4 row groups x 128 rows; 37 CTAs/group: r<20 heavy (layer1, K=640, p0=r*64);
// r>=20 light (layer0, K=320): r2=r-20 owns tile r2 and (r2<3) also 17+r2.
// Tile 128 rows x 64 perm cols; 16 warps 4x4; warp tile 32x16; thread 4 cells.
// B resident in smem, XOR-swizzled, unpadded. A via cp.async.bulk, 2-stage ring, k-chunk 64.
__global__ void __launch_bounds__(TPB, 1)
lstm_pers(const int* __restrict__ x, float* __restrict__ out) {
    extern __shared__ __align__(16) char dsm[];
    const uint32_t sbase = (uint32_t)__cvta_generic_to_shared(dsm);
    const uint32_t mb0 = sbase + MBAR_OFF;
    const uint32_t BresB = sbase + BRES_OFF;

    const int tx = threadIdx.x;
    const int lane = tx & 31, wid = tx >> 5;
    const int wrow = wid >> 2, wcol = wid & 3;
    const int g_ = lane >> 2, q_ = lane & 3;
    const int sub = lane >> 3, subrow = lane & 7;
    const int b = blockIdx.x;
    const int grp = b / 37, r = b - grp * 37;
    const int heavy = (r < 20);
    const int n0 = grp * 128;
    const int Kdim = heavy ? 640 : 320;
    const int K4 = Kdim * 4;
    const int nch = Kdim >> 6;                     // 10 heavy, 5 light
    const int ntile = heavy ? 1 : ((r - 20) < 3 ? 2 : 1);
    int p0s[2];
    if (heavy) { p0s[0] = r * 64; p0s[1] = 0; }
    else       { p0s[0] = (r - 20) * 64; p0s[1] = (17 + (r - 20)) * 64; }

    // ---- one-time: init mbars, load resident B (swizzled) ----
    if (tx == 0) {
#pragma unroll
        for (int i = 0; i < 2; ++i)
            asm volatile("mbarrier.init.shared.b64 [%0], %1;" :: "r"(mb0 + i * 8), "r"(1u) : "memory");
    }
    for (int ti = 0; ti < ntile; ++ti) {
        const float* Wg = heavy ? (d_W1m + p0s[ti] * 640) : (d_W0m + p0s[ti] * 320);
        const int nseg = Kdim >> 2;
        for (int i = tx; i < 64 * nseg; i += TPB) {
            const int col = i / nseg, seg = i - col * nseg;
            const int dstb = ti * BSLOT_B + col * K4 + ((seg * 16) ^ ((col & 7) << 4));
            *reinterpret_cast<float4*>(dsm + BRES_OFF + dstb) =
                *reinterpret_cast<const float4*>(Wg + col * Kdim + seg * 4);
        }
    }
    __syncthreads();

    // ldsm lane constants
    const uint32_t xr = (uint32_t)(subrow << 4);
    uint32_t rbaseA[2];
#pragma unroll
    for (int mi = 0; mi < 2; ++mi)
        rbaseA[mi] = (uint32_t)((wrow * 32 + mi * 16 + (sub & 1) * 8 + subrow) * 256);
    const uint32_t s16A = (uint32_t)((sub >> 1) * 16);
    const uint32_t colbaseB = (uint32_t)((wcol * 16 + (sub >> 1) * 8 + subrow) * K4);
    const uint32_t s16B = (uint32_t)((sub & 1) * 16);

    int ph[2] = {0, 0};

    for (int s = 0; s < 129; ++s) {
        const int par = s & 1;
        const int active = heavy ? (s >= 1) : (s < 128);
        if (active) {
            const float* Asrc = heavy ? d_A1c[par] : d_A0c[par];
            const int u = heavy ? (s - 1) : s;
            float* Cst = heavy ? d_C1 : d_C0;

            for (int ti = 0; ti < ntile; ++ti) {
                const int p0 = p0s[ti];
                const uint32_t Bti = BresB + (uint32_t)(ti * BSLOT_B) + colbaseB;

                // prefetch c-state + labels
                float cpre[2][2];
                int labv[2][2];
                const int cellg = (p0 >> 2) + wcol * 4 + q_;
#pragma unroll
                for (int mi = 0; mi < 2; ++mi)
#pragma unroll
                    for (int rs = 0; rs < 2; ++rs) {
                        const int n = n0 + wrow * 32 + mi * 16 + g_ + rs * 8;
                        if (!heavy) labv[mi][rs] = x[u * 512 + n];
                        cpre[mi][rs] = Cst[n * 320 + cellg];
                    }

                float acc[2][2][4];
#pragma unroll
                for (int mi = 0; mi < 2; ++mi)
#pragma unroll
                    for (int ni = 0; ni < 2; ++ni)
#pragma unroll
                        for (int e = 0; e < 4; ++e) acc[mi][ni][e] = 0.0f;

                if (tx == 0) {
                    bulk_ld(sbase,          Asrc + 0 * 32768 + n0 * 64, mb0);
                    bulk_ld(sbase + STG_B,  Asrc + 1 * 32768 + n0 * 64, mb0 + 8);
                }

                for (int ch = 0; ch < nch; ++ch) {
                    const int sl = ch & 1;
                    waitp(mb0 + sl * 8, ph[sl]); ph[sl] ^= 1;
                    const uint32_t stA = sbase + (uint32_t)sl * STG_B;
                    const uint32_t chB = Bti + (uint32_t)ch * 256;
#pragma unroll
                    for (int ks = 0; ks < 8; ++ks) {
                        const uint32_t swzA = ((uint32_t)(ks * 32) + s16A) ^ xr;
                        const uint32_t swzB = ((uint32_t)(ks * 32) + s16B) ^ xr;
                        uint32_t a[2][4], bb[4];
                        ldm4(a[0][0], a[0][1], a[0][2], a[0][3], stA + rbaseA[0] + swzA);
                        ldm4(a[1][0], a[1][1], a[1][2], a[1][3], stA + rbaseA[1] + swzA);
                        ldm4(bb[0], bb[1], bb[2], bb[3], chB + swzB);
#pragma unroll
                        for (int mi = 0; mi < 2; ++mi) {
                            mma8(acc[mi][0], a[mi], bb[0], bb[1]);
                            mma8(acc[mi][1], a[mi], bb[2], bb[3]);
                        }
                    }
                    __syncthreads();                 // all warps done with stage sl
                    if (tx == 0 && ch + 2 < nch)
                        bulk_ld(sbase + sl * STG_B,
                                Asrc + (size_t)(ch + 2) * 32768 + n0 * 64, mb0 + sl * 8);
                }

                // ---- epilogue: 2 mi x 2 rows, 1 cell, all 4 gates in-regs ----
#pragma unroll
                for (int mi = 0; mi < 2; ++mi) {
#pragma unroll
                    for (int rs = 0; rs < 2; ++rs) {
                        const int n = n0 + wrow * 32 + mi * 16 + g_ + rs * 8;
                        const float* tb = heavy ? d_B1 : (d_T0 + labv[mi][rs] * 1280);
                        const float4 t = *reinterpret_cast<const float4*>(tb + cellg * 4);
                        const float pi = acc[mi][0][rs * 2 + 0] + t.x;
                        const float pf = acc[mi][0][rs * 2 + 1] + t.y;
                        const float pg = acc[mi][1][rs * 2 + 0] + t.z;
                        const float po = acc[mi][1][rs * 2 + 1] + t.w;
                        const float ii = sigf(pi), ff = sigf(pf);
                        const float gg = tanhf_(pg), oo = sigf(po);
                        const int ci = n * 320 + cellg;
                        const float c = ff * cpre[mi][rs] + ii * gg;
                        Cst[ci] = c;
                        const float h = oo * tanhf_(c);
                        const float hr = tf32_rne(h);
                        const int wsw = aswz64(n, cellg & 63);
                        if (heavy) {
                            out[(size_t)u * NC + ci] = h;
                            d_A1c[par ^ 1][(5 + (cellg >> 6)) * 32768 + wsw] = hr;
                            if (u == 127) { out[GSZ + NC + ci] = h; out[GSZ + 3 * NC + ci] = c; }
                        } else {
                            d_A0c[par ^ 1][(cellg >> 6) * 32768 + wsw] = hr;
                            d_A1c[par ^ 1][(cellg >> 6) * 32768 + wsw] = hr;
                            if (u == 127) { out[GSZ + ci] = h; out[GSZ + 2 * NC + ci] = c; }
                        }
                    }
                }
            }
        }

        // ---- group barrier (37 CTAs, release/acquire) ----
        __syncthreads();
        if (tx == 0) {
            __threadfence();
            const unsigned arrived = atomicAdd(&g_cntA[grp * 32], 1u);
            if (arrived == 36u) {
                g_cntA[grp * 32] = 0u;
                __threadfence();
                st_rel(&g_genA[grp * 32], (unsigned)(s + 1));
            } else {
                while (ld_acq(&g_genA[grp * 32]) <= (unsigned)s) __nanosleep(32);
            }
        }
        __syncthreads();
    }
}

// ---------------- launcher ----------------
extern "C" void kernel_launch(void* const* d_in, const int* in_sizes, int n_in,
                              void* d_out, int out_size) {
    const int*   x    = (const int*)d_in[0];
    const float* h0   = (const float*)d_in[1];
    const float* c0   = (const float*)d_in[2];
    const float* emb  = (const float*)d_in[3];
    const float* w_ih = (const float*)d_in[4];
    const float* w_hh = (const float*)d_in[5];
    const float* b_ih = (const float*)d_in[6];
    const float* b_hh = (const float*)d_in[7];

    cudaFuncSetAttribute(lstm_pers, cudaFuncAttributeMaxDynamicSharedMemorySize, SMEM_DYN);

    prep_wt<<<512, 256>>>(w_ih, w_hh);
    prep_t0<<<290, 128>>>(emb, w_ih, b_ih, b_hh);
    prep_state<<<256, 256>>>(h0, c0, b_ih, b_hh);
    lstm_pers<<<NBLK, TPB, SMEM_DYN>>>(x, (float*)d_out);
}